// round 16
// baseline (speedup 1.0000x reference)
#include <cuda_runtime.h>
#include <cuda_bf16.h>
#include <cstdint>
#include <math.h>

#define NTOK 8192
#define DIM  1024
#define NEXP 8
#define DFF  4096
#define CAP  1280   // int(8192/8 * 1.25)
#define NMT  10     // CAP/128
#define PERSIST_CTAS 296   // 148 SMs * 2 CTAs/SM

// ---------------- scratch (device globals; no allocation allowed) ----------
__device__ __nv_bfloat16 g_xh[(size_t)NTOK * DIM];
__device__ __nv_bfloat16 g_xl[(size_t)NTOK * DIM];
__device__ __nv_bfloat16 g_W1h[(size_t)NEXP * DIM * DFF];
__device__ __nv_bfloat16 g_W1l[(size_t)NEXP * DIM * DFF];
__device__ __nv_bfloat16 g_W2h[(size_t)NEXP * DFF * DIM];
__device__ __nv_bfloat16 g_W2l[(size_t)NEXP * DFF * DIM];
__device__ __nv_bfloat16 g_hh[(size_t)NEXP * CAP * DFF];
__device__ __nv_bfloat16 g_hl[(size_t)NEXP * CAP * DFF];
__device__ int   g_eidx[NTOK];
__device__ float g_gate[NTOK];
__device__ int   g_kept[NTOK];
__device__ int   g_slot2tok[NEXP * CAP];
__device__ float g_probs_sum[NEXP];
__device__ int   g_count[NEXP];

// ---------------- init ------------------------------------------------------
__global__ void init_kernel() {
    if (threadIdx.x < NEXP) g_probs_sum[threadIdx.x] = 0.f;
}

// ---------------- router: logits, softmax, argmax, gate --------------------
__global__ void router_kernel(const float* __restrict__ x,
                              const float* __restrict__ Wr) {
    __shared__ float s_sum[NEXP];
    if (threadIdx.x < NEXP) s_sum[threadIdx.x] = 0.f;
    __syncthreads();

    int gwarp = (blockIdx.x * blockDim.x + threadIdx.x) >> 5;
    int lane  = threadIdx.x & 31;
    if (gwarp < NTOK) {
        const float* xr = x + (size_t)gwarp * DIM;
        float acc[NEXP];
#pragma unroll
        for (int e = 0; e < NEXP; e++) acc[e] = 0.f;
        for (int d = lane; d < DIM; d += 32) {
            float xv = xr[d];
            const float* wr = Wr + d * NEXP;
#pragma unroll
            for (int e = 0; e < NEXP; e++) acc[e] += xv * wr[e];
        }
#pragma unroll
        for (int e = 0; e < NEXP; e++)
#pragma unroll
            for (int o = 16; o; o >>= 1)
                acc[e] += __shfl_xor_sync(0xffffffffu, acc[e], o);

        if (lane == 0) {
            float mx = acc[0]; int ai = 0;
#pragma unroll
            for (int e = 1; e < NEXP; e++)
                if (acc[e] > mx) { mx = acc[e]; ai = e; }
            float p[NEXP], den = 0.f;
#pragma unroll
            for (int e = 0; e < NEXP; e++) { p[e] = expf(acc[e] - mx); den += p[e]; }
            float inv = 1.f / den;
#pragma unroll
            for (int e = 0; e < NEXP; e++) {
                p[e] *= inv;
                atomicAdd(&s_sum[e], p[e]);
            }
            g_eidx[gwarp] = ai;
            g_gate[gwarp] = p[ai];
        }
    }
    __syncthreads();
    if (threadIdx.x < NEXP) atomicAdd(&g_probs_sum[threadIdx.x], s_sum[threadIdx.x]);
}

// ---------------- scan: order-exact per-expert positions + capacity --------
__global__ void scan_kernel() {
    __shared__ int sbase[NEXP];
    __shared__ int wpre[NEXP][32];
    __shared__ int ctot[NEXP];
    int tid = threadIdx.x, lane = tid & 31, wid = tid >> 5;

    for (int i = tid; i < NEXP * CAP; i += 1024) g_slot2tok[i] = NTOK;
    if (tid < NEXP) sbase[tid] = 0;
    __syncthreads();

    for (int c0 = 0; c0 < NTOK; c0 += 1024) {
        int tok = c0 + tid;
        int e = g_eidx[tok];
        int myrank = 0;
#pragma unroll
        for (int e2 = 0; e2 < NEXP; e2++) {
            unsigned m = __ballot_sync(0xffffffffu, e == e2);
            if (e == e2) myrank = __popc(m & ((1u << lane) - 1u));
            if (lane == 0) wpre[e2][wid] = __popc(m);
        }
        __syncthreads();
        if (wid < NEXP) {
            int v = wpre[wid][lane];
            int incl = v;
#pragma unroll
            for (int o = 1; o < 32; o <<= 1) {
                int t = __shfl_up_sync(0xffffffffu, incl, o);
                if (lane >= o) incl += t;
            }
            wpre[wid][lane] = incl - v;
            if (lane == 31) ctot[wid] = incl;
        }
        __syncthreads();
        int pos  = sbase[e] + wpre[e][wid] + myrank;
        int kept = (pos < CAP) ? 1 : 0;
        g_kept[tok] = kept;
        if (kept) g_slot2tok[e * CAP + pos] = tok;
        else      g_gate[tok] = 0.f;
        __syncthreads();
        if (tid < NEXP) sbase[tid] += ctot[tid];
        __syncthreads();
    }
    if (tid < NEXP) g_count[tid] = sbase[tid] < CAP ? sbase[tid] : CAP;
}

// ---------------- bf16 split: v = hi + lo (both rn) ------------------------
__device__ __forceinline__ void bf16_split(float v, __nv_bfloat16& h, __nv_bfloat16& l) {
    h = __float2bfloat16(v);
    l = __float2bfloat16(v - __bfloat162float(h));
}

// elementwise split kernel: 4 elems/thread (coalesced)
__global__ void split_kernel(const float* __restrict__ src,
                             __nv_bfloat16* __restrict__ dh,
                             __nv_bfloat16* __restrict__ dl, size_t n4) {
    size_t i = (size_t)blockIdx.x * blockDim.x + threadIdx.x;
    if (i >= n4) return;
    float4 v = ((const float4*)src)[i];
    __nv_bfloat16 h0, h1, h2, h3, l0, l1, l2, l3;
    bf16_split(v.x, h0, l0);
    bf16_split(v.y, h1, l1);
    bf16_split(v.z, h2, l2);
    bf16_split(v.w, h3, l3);
    ((__nv_bfloat162*)dh)[i * 2]     = __nv_bfloat162(h0, h1);
    ((__nv_bfloat162*)dh)[i * 2 + 1] = __nv_bfloat162(h2, h3);
    ((__nv_bfloat162*)dl)[i * 2]     = __nv_bfloat162(l0, l1);
    ((__nv_bfloat162*)dl)[i * 2 + 1] = __nv_bfloat162(l2, l3);
}

// ---------------- fast branch-free tanh + GELU ------------------------------
__device__ __forceinline__ float fast_tanh(float u) {
    float ex;
    asm("ex2.approx.f32 %0, %1;" : "=f"(ex) : "f"(u * 2.885390082f)); // e^{2u}
    float rc;
    asm("rcp.approx.f32 %0, %1;" : "=f"(rc) : "f"(ex + 1.f));
    return 1.f - 2.f * rc;
}
__device__ __forceinline__ float gelu_tanh(float v) {
    const float k0 = 0.7978845608028654f;
    const float k1 = 0.044715f;
    float u = k0 * (v + k1 * v * v * v);
    return 0.5f * v * (1.f + fast_tanh(u));
}

// ============ tensor-core GEMM via 3x bf16 mma.sync (split operands) ========
// PERSISTENT version: 296 CTAs loop over (e, mt, nt) tiles, killing the
// wave-quantization tail (GEMM2 was 640 CTAs over 296 slots = 2.16 waves).
// CTA tile 128(M) x 128(N) x 32(K). 256 threads = 8 warps (4m x 2n).
// a*b ~= a0*b0 + a0*b1 + a1*b0. 2-stage cp.async; 2 CTAs/SM.
// MODE 0: A = gathered split-x rows -> epilogue gelu(v+b1) split into g_hh/g_hl
// MODE 1: A = split-h rows          -> epilogue gate*(v+b2) scattered to out

#define ASTR 40     // bf16 per A row (32 + 8 pad)
#define BSTR 136    // bf16 per B row (128 + 8 pad)
#define OFF_AH 0
#define OFF_AL (128 * ASTR)                  // 5120
#define OFF_BH (2 * 128 * ASTR)              // 10240
#define OFF_BL (2 * 128 * ASTR + 32 * BSTR)  // 14592
#define STAGE_ELEMS (2 * 128 * ASTR + 2 * 32 * BSTR)   // 18944 bf16 = 37888 B
#define GEMM_SMEM (STAGE_ELEMS * 2 * 2)                // 75776 B

__device__ __forceinline__ void cpa16(uint32_t dst, const void* src, int src_size) {
    asm volatile("cp.async.cg.shared.global [%0], [%1], 16, %2;"
                 :: "r"(dst), "l"(src), "r"(src_size));
}
__device__ __forceinline__ void cpa_commit() {
    asm volatile("cp.async.commit_group;" ::: "memory");
}
template<int N> __device__ __forceinline__ void cpa_wait() {
    asm volatile("cp.async.wait_group %0;" :: "n"(N) : "memory");
}

__device__ __forceinline__ void ldsm_x4(uint32_t* r, uint32_t a) {
    asm volatile("ldmatrix.sync.aligned.m8n8.x4.shared.b16 {%0,%1,%2,%3}, [%4];"
                 : "=r"(r[0]), "=r"(r[1]), "=r"(r[2]), "=r"(r[3]) : "r"(a));
}
__device__ __forceinline__ void ldsm_x4_t(uint32_t* r, uint32_t a) {
    asm volatile("ldmatrix.sync.aligned.m8n8.x4.trans.shared.b16 {%0,%1,%2,%3}, [%4];"
                 : "=r"(r[0]), "=r"(r[1]), "=r"(r[2]), "=r"(r[3]) : "r"(a));
}

__device__ __forceinline__ void mma_bf16(float* d, const uint32_t* a, const uint32_t* b) {
    asm volatile(
        "mma.sync.aligned.m16n8k16.row.col.f32.bf16.bf16.f32 "
        "{%0,%1,%2,%3}, {%4,%5,%6,%7}, {%8,%9}, {%0,%1,%2,%3};"
        : "+f"(d[0]), "+f"(d[1]), "+f"(d[2]), "+f"(d[3])
        : "r"(a[0]), "r"(a[1]), "r"(a[2]), "r"(a[3]), "r"(b[0]), "r"(b[1]));
}

// one stage load for a given tile (helper macro-ish function)
template<int MODE>
__device__ __forceinline__ void load_stage_fn(
    uint32_t smem_b, int s,
    const __nv_bfloat16* aph, const __nv_bfloat16* apl, int asz,
    const __nv_bfloat16* bph, const __nv_bfloat16* bpl,
    uint32_t sa, uint32_t sb, int k0, int NB) {
    uint32_t base = smem_b + s * STAGE_ELEMS * 2;
    cpa16(base + OFF_AH * 2 + sa,      aph + k0, asz);
    cpa16(base + OFF_AH * 2 + sa + 16, aph + k0 + 8, asz);
    cpa16(base + OFF_AL * 2 + sa,      apl + k0, asz);
    cpa16(base + OFF_AL * 2 + sa + 16, apl + k0 + 8, asz);
    const __nv_bfloat16* bh = bph + (size_t)k0 * NB;
    const __nv_bfloat16* bl = bpl + (size_t)k0 * NB;
    cpa16(base + OFF_BH * 2 + sb,      bh, 16);
    cpa16(base + OFF_BH * 2 + sb + 16, bh + 8, 16);
    cpa16(base + OFF_BL * 2 + sb,      bl, 16);
    cpa16(base + OFF_BL * 2 + sb + 16, bl + 8, 16);
    cpa_commit();
}

template<int KDIM, int NB, int MODE>
__global__ __launch_bounds__(256, 2)
void gemm_mma(const float* __restrict__ bias, float* __restrict__ out) {
    extern __shared__ __align__(16) __nv_bfloat16 smem[];
    const int tid = threadIdx.x;
    const int lane = tid & 31;
    const int wid  = tid >> 5;
    const int wm = (wid & 3) * 32;        // warp m offset
    const int wn = (wid >> 2) * 64;       // warp n offset

    const int NTX = NB / 128;             // n-tiles
    const int TOTAL = NEXP * NMT * NTX;

    const uint32_t smem_b = (uint32_t)__cvta_generic_to_shared(smem);
    const int arow = tid >> 1;
    const int ahalf = tid & 1;
    const uint32_t sa = (arow * ASTR + ahalf * 16) * 2;           // bytes
    const uint32_t sb = ((tid >> 3) * BSTR + (tid & 7) * 16) * 2; // bytes
    const int NC = KDIM / 32;

    // ldmatrix lane addressing (tile-invariant)
    const int lr = lane & 7, lg = lane >> 3;
    const int a_row = wm + (lg & 1) * 8 + lr;
    const int a_col = (lg >> 1) * 8;
    const int b_row = (lg & 1) * 8 + lr;
    const int b_col = wn + (lg >> 1) * 8;

    for (int t = blockIdx.x; t < TOTAL; t += PERSIST_CTAS) {
        const int nt = t % NTX;
        const int mt = (t / NTX) % NMT;
        const int e  = t / (NTX * NMT);

        // ---- per-tile source pointers ----
        const __nv_bfloat16 *aph, *apl;
        int asz = 16;
        if (MODE == 0) {
            int tok = g_slot2tok[e * CAP + mt * 128 + arow];
            if (tok >= NTOK) { tok = 0; asz = 0; }
            aph = g_xh + (size_t)tok * DIM + ahalf * 16;
            apl = g_xl + (size_t)tok * DIM + ahalf * 16;
        } else {
            size_t off = (size_t)(e * CAP + mt * 128 + arow) * KDIM + ahalf * 16;
            aph = g_hh + off;
            apl = g_hl + off;
        }
        const size_t boff = (size_t)e * KDIM * NB + (size_t)(tid >> 3) * NB
                          + nt * 128 + (tid & 7) * 16;
        const __nv_bfloat16* bph = ((MODE == 0) ? g_W1h : g_W2h) + boff;
        const __nv_bfloat16* bpl = ((MODE == 0) ? g_W1l : g_W2l) + boff;

        load_stage_fn<MODE>(smem_b, 0, aph, apl, asz, bph, bpl, sa, sb, 0, NB);
        load_stage_fn<MODE>(smem_b, 1, aph, apl, asz, bph, bpl, sa, sb, 32, NB);

        float acc[2][8][4];
#pragma unroll
        for (int mi = 0; mi < 2; mi++)
#pragma unroll
            for (int nf = 0; nf < 8; nf++)
#pragma unroll
                for (int q = 0; q < 4; q++) acc[mi][nf][q] = 0.f;

        for (int c = 0; c < NC; c++) {
            cpa_wait<1>();
            __syncthreads();

            uint32_t base = smem_b + (c & 1) * STAGE_ELEMS * 2;

#pragma unroll
            for (int ks = 0; ks < 2; ks++) {
                uint32_t ah[2][4], al[2][4];
#pragma unroll
                for (int mi = 0; mi < 2; mi++) {
                    uint32_t addr = base +
                        ((a_row + mi * 16) * ASTR + ks * 16 + a_col) * 2;
                    ldsm_x4(ah[mi], addr + OFF_AH * 2);
                    ldsm_x4(al[mi], addr + OFF_AL * 2);
                }
#pragma unroll
                for (int nf2 = 0; nf2 < 4; nf2++) {
                    uint32_t addr = base +
                        ((ks * 16 + b_row) * BSTR + b_col + nf2 * 16) * 2;
                    uint32_t rh[4], rl[4];
                    ldsm_x4_t(rh, addr + OFF_BH * 2);
                    ldsm_x4_t(rl, addr + OFF_BL * 2);
#pragma unroll
                    for (int mi = 0; mi < 2; mi++) {
                        mma_bf16(acc[mi][nf2 * 2],     ah[mi], rh);
                        mma_bf16(acc[mi][nf2 * 2 + 1], ah[mi], rh + 2);
                    }
#pragma unroll
                    for (int mi = 0; mi < 2; mi++) {
                        mma_bf16(acc[mi][nf2 * 2],     ah[mi], rl);
                        mma_bf16(acc[mi][nf2 * 2 + 1], ah[mi], rl + 2);
                    }
#pragma unroll
                    for (int mi = 0; mi < 2; mi++) {
                        mma_bf16(acc[mi][nf2 * 2],     al[mi], rh);
                        mma_bf16(acc[mi][nf2 * 2 + 1], al[mi], rh + 2);
                    }
                }
            }
            __syncthreads();
            if (c + 2 < NC)
                load_stage_fn<MODE>(smem_b, c & 1, aph, apl, asz, bph, bpl,
                                    sa, sb, (c + 2) * 32, NB);
            else
                cpa_commit();
        }

        // ---- epilogue ----
        const float* bias_p = bias + e * NB + nt * 128;
#pragma unroll
        for (int mi = 0; mi < 2; mi++) {
#pragma unroll
            for (int rr = 0; rr < 2; rr++) {
                int lrow = wm + mi * 16 + (lane >> 2) + rr * 8;
                int slot = e * CAP + mt * 128 + lrow;
                if (MODE == 0) {
                    size_t rowoff = (size_t)slot * DFF + nt * 128;
#pragma unroll
                    for (int nf = 0; nf < 8; nf++) {
                        int cn = wn + nf * 8 + (lane & 3) * 2;
                        float v0 = gelu_tanh(acc[mi][nf][rr * 2 + 0] + bias_p[cn]);
                        float v1 = gelu_tanh(acc[mi][nf][rr * 2 + 1] + bias_p[cn + 1]);
                        __nv_bfloat16 h0, h1, l0, l1;
                        bf16_split(v0, h0, l0);
                        bf16_split(v1, h1, l1);
                        *(__nv_bfloat162*)(g_hh + rowoff + cn) = __nv_bfloat162(h0, h1);
                        *(__nv_bfloat162*)(g_hl + rowoff + cn) = __nv_bfloat162(l0, l1);
                    }
                } else {
                    int tok = g_slot2tok[slot];
                    if (tok < NTOK) {
                        float gt = g_gate[tok];
                        float* orow = out + (size_t)tok * DIM + nt * 128;
#pragma unroll
                        for (int nf = 0; nf < 8; nf++) {
                            int cn = wn + nf * 8 + (lane & 3) * 2;
                            float2 v;
                            v.x = gt * (acc[mi][nf][rr * 2 + 0] + bias_p[cn]);
                            v.y = gt * (acc[mi][nf][rr * 2 + 1] + bias_p[cn + 1]);
                            *(float2*)(orow + cn) = v;
                        }
                    }
                }
            }
        }
        __syncthreads();   // all warps done with epilogue before next tile's loads
    }
}

// ---------------- passthrough for dropped tokens ---------------------------
__global__ void passthrough_kernel(const float* __restrict__ x,
                                   float* __restrict__ out) {
    int tok = blockIdx.x;
    if (g_kept[tok]) return;
    const float4* src = (const float4*)(x + (size_t)tok * DIM);
    float4* dst = (float4*)(out + (size_t)tok * DIM);
    dst[threadIdx.x] = src[threadIdx.x];
}

// ---------------- aux loss --------------------------------------------------
__global__ void aux_kernel(float* __restrict__ out, int out_size) {
    if (out_size <= NTOK * DIM) return;
    float s = 0.f;
    for (int e = 0; e < NEXP; e++) {
        float frac = (float)g_count[e] / (float)NTOK;
        float pm   = g_probs_sum[e] / (float)NTOK;
        s += frac * pm;
    }
    out[NTOK * DIM] = 0.01f * (float)NEXP * s;
}

// ---------------- launch ----------------------------------------------------
extern "C" void kernel_launch(void* const* d_in, const int* in_sizes, int n_in,
                              void* d_out, int out_size) {
    const float* x  = (const float*)d_in[0];
    const float* Wr = (const float*)d_in[1];
    const float* W1 = (const float*)d_in[2];
    const float* b1 = (const float*)d_in[3];
    const float* W2 = (const float*)d_in[4];
    const float* b2 = (const float*)d_in[5];
    float* out = (float*)d_out;

    cudaFuncSetAttribute(gemm_mma<DIM, DFF, 0>,
                         cudaFuncAttributeMaxDynamicSharedMemorySize, GEMM_SMEM);
    cudaFuncSetAttribute(gemm_mma<DFF, DIM, 1>,
                         cudaFuncAttributeMaxDynamicSharedMemorySize, GEMM_SMEM);

    init_kernel<<<1, 32>>>();
    router_kernel<<<NTOK / 8, 256>>>(x, Wr);
    scan_kernel<<<1, 1024>>>();

    // bf16 splits of x, W1, W2
    {
        __nv_bfloat16 *xh, *xl, *w1h, *w1l, *w2h, *w2l;
        cudaGetSymbolAddress((void**)&xh,  g_xh);
        cudaGetSymbolAddress((void**)&xl,  g_xl);
        cudaGetSymbolAddress((void**)&w1h, g_W1h);
        cudaGetSymbolAddress((void**)&w1l, g_W1l);
        cudaGetSymbolAddress((void**)&w2h, g_W2h);
        cudaGetSymbolAddress((void**)&w2l, g_W2l);
        size_t nx = (size_t)NTOK * DIM / 4;
        size_t nw = (size_t)NEXP * DIM * DFF / 4;
        split_kernel<<<(unsigned)((nx + 255) / 256), 256>>>(x,  xh,  xl,  nx);
        split_kernel<<<(unsigned)((nw + 255) / 256), 256>>>(W1, w1h, w1l, nw);
        split_kernel<<<(unsigned)((nw + 255) / 256), 256>>>(W2, w2h, w2l, nw);
    }

    // GEMM1: h = gelu(gather(x) @ W1 + b1)   [M=CAP, N=DFF, K=DIM]
    gemm_mma<DIM, DFF, 0><<<PERSIST_CTAS, 256, GEMM_SMEM>>>(b1, nullptr);

    passthrough_kernel<<<NTOK, 256>>>(x, out);

    // GEMM2: out[tok] = gate * (h @ W2 + b2) [M=CAP, N=DIM, K=DFF]
    gemm_mma<DFF, DIM, 1><<<PERSIST_CTAS, 256, GEMM_SMEM>>>(b2, out);

    aux_kernel<<<1, 1>>>(out, out_size);
}